// round 2
// baseline (speedup 1.0000x reference)
#include <cuda_runtime.h>
#include <cstdint>

#define LEAK 0.5f
typedef unsigned long long ull;

// Intermediate activation scratch (allocation-free: __device__ globals)
__device__ float g_buf1[32 * 128 * 111 * 111]; // after stage 1 (202 MB)
__device__ float g_buf2[32 * 64 * 54 * 54];    // after stage 2 (24 MB)
__device__ float g_buf3[32 * 32 * 26 * 26];    // after stage 3 (2.8 MB)

__device__ __forceinline__ float* buf_ptr(int which) {
    return which == 1 ? g_buf1 : (which == 2 ? g_buf2 : g_buf3);
}

// ---- packed fp32x2 helpers (Blackwell FFMA2 path) -------------------------
__device__ __forceinline__ ull pk2(float lo, float hi) {
    ull r;
    asm("mov.b64 %0, {%1,%2};" : "=l"(r) : "f"(lo), "f"(hi));
    return r;
}
__device__ __forceinline__ void ffma2(ull& d, ull a, ull b) {
    asm("fma.rn.f32x2 %0, %1, %2, %0;" : "+l"(d) : "l"(a), "l"(b));
}
__device__ __forceinline__ float2 unpk2(ull v) {
    float2 r;
    asm("mov.b64 {%0,%1}, %2;" : "=f"(r.x), "=f"(r.y) : "l"(v));
    return r;
}

// ---------------------------------------------------------------------------
// Stage 1: conv(1->128, 3x3) + bias + leaky + maxpool2
// x[32,1,224,224] -> g_buf1[32,128,111,111]
// Block: 256 threads = 16x16 pooled tile; dx (pool cols) packed into f32x2.
// ---------------------------------------------------------------------------
__global__ __launch_bounds__(256)
void k_conv1(const float* __restrict__ x, const float* __restrict__ w1,
             const float* __restrict__ b1)
{
    __shared__ __align__(16) float sx[34][36];
    __shared__ __align__(16) ull   swd[128][9];  // duplicated {w,w} pairs
    __shared__ float sb[128];

    const int n   = blockIdx.z;
    const int ph0 = blockIdx.y * 16, pw0 = blockIdx.x * 16;
    const int ih0 = 2 * ph0, iw0 = 2 * pw0;
    const int t   = threadIdx.x;

    const float* xn = x + (size_t)n * 224 * 224;
    for (int i = t; i < 34 * 34; i += 256) {
        int r = i / 34, c = i % 34;
        int ir = ih0 + r, ic = iw0 + c;
        sx[r][c] = (ir < 224 && ic < 224) ? xn[ir * 224 + ic] : 0.f;
    }
    for (int i = t; i < 128 * 9; i += 256) {
        float s = (w1[i] >= 0.f) ? 1.f : -1.f;
        swd[i / 9][i % 9] = pk2(s, s);
    }
    if (t < 128) sb[t] = b1[t];
    __syncthreads();

    const int py = t >> 4, px = t & 15;
    const int ph = ph0 + py, pw = pw0 + px;
    const bool valid = (ph < 111) && (pw < 111);

    // packed x pairs: xr[kw][r] = (x[r][kw], x[r][kw+1]), hoisted out of co loop
    ull xr[3][4];
#pragma unroll
    for (int r = 0; r < 4; r++) {
        float x0 = sx[2 * py + r][2 * px + 0];
        float x1 = sx[2 * py + r][2 * px + 1];
        float x2 = sx[2 * py + r][2 * px + 2];
        float x3 = sx[2 * py + r][2 * px + 3];
        xr[0][r] = pk2(x0, x1);
        xr[1][r] = pk2(x1, x2);
        xr[2][r] = pk2(x2, x3);
    }

    float* op = g_buf1 + ((size_t)n * 128) * (111 * 111) + ph * 111 + pw;

#pragma unroll 2
    for (int co = 0; co < 128; co++) {
        ull acc0 = 0ull, acc1 = 0ull;  // dy = 0,1 ; packed over dx
#pragma unroll
        for (int kh = 0; kh < 3; kh++)
#pragma unroll
            for (int kw = 0; kw < 3; kw++) {
                ull wv = swd[co][kh * 3 + kw];
                ffma2(acc0, xr[kw][0 + kh], wv);
                ffma2(acc1, xr[kw][1 + kh], wv);
            }
        float2 a = unpk2(acc0), b2 = unpk2(acc1);
        float m = fmaxf(fmaxf(a.x, a.y), fmaxf(b2.x, b2.y));
        m += sb[co];
        m = (m >= 0.f) ? m : LEAK * m;
        if (valid) op[(size_t)co * (111 * 111)] = m;
    }
}

// ---------------------------------------------------------------------------
// Stages 2/3: conv(CI->CO, 3x3) + bias + leaky + maxpool2, f32x2-packed.
// Block: 256 thr = 64 pooled pixels (8x8) x 4 co-groups; per thread:
// 2 (pool rows) x 4 co f32x2 accumulators, packed over the 2 pool cols.
// ---------------------------------------------------------------------------
template<int CI, int CO, int HIN, int POUT, int IBUF, int OBUF>
__global__ __launch_bounds__(256)
void k_conv_pool(const float* __restrict__ wg, const float* __restrict__ bg)
{
    constexpr int CI_CHUNK = 16;
    constexpr int CO_TILE  = 16;
    constexpr int NTX      = (POUT + 7) / 8;

    __shared__ __align__(16) float sx[CI_CHUNK][18][20];
    __shared__ __align__(16) ull   swd[CI_CHUNK][9][CO_TILE]; // {w,w} pairs

    const float* in  = buf_ptr(IBUF);
    float*       out = buf_ptr(OBUF);

    const int n   = blockIdx.z;
    const int co0 = blockIdx.y * CO_TILE;
    const int ty  = blockIdx.x / NTX, tx = blockIdx.x % NTX;
    const int ph0 = ty * 8, pw0 = tx * 8;
    const int ih0 = 2 * ph0, iw0 = 2 * pw0;

    const int t   = threadIdx.x;
    const int pix = t & 63, cg = t >> 6;
    const int py  = pix >> 3, px = pix & 7;

    const float* xn = in + ((size_t)n * CI) * (HIN * HIN);

    ull acc[2][4];  // [dy][co_j], packed over dx
#pragma unroll
    for (int dy = 0; dy < 2; dy++)
#pragma unroll
        for (int j = 0; j < 4; j++) acc[dy][j] = 0ull;

    for (int cc = 0; cc < CI; cc += CI_CHUNK) {
        // stage input tile [16ch][18][18] (padded rows)
        for (int i = t; i < CI_CHUNK * 18 * 18; i += 256) {
            int ci  = i / (18 * 18);
            int rem = i % (18 * 18);
            int r = rem / 18, c = rem % 18;
            int ir = ih0 + r, ic = iw0 + c;
            float v = (ir < HIN && ic < HIN)
                          ? xn[(size_t)(cc + ci) * (HIN * HIN) + ir * HIN + ic]
                          : 0.f;
            sx[ci][r][c] = v;
        }
        // stage binarized duplicated weight pairs [ci][tap][co]
        for (int i = t; i < CI_CHUNK * 9 * CO_TILE; i += 256) {
            int co  = i % CO_TILE;
            int rem = i / CO_TILE;
            int k   = rem % 9;
            int ci  = rem / 9;
            float v = wg[(((size_t)(co0 + co)) * CI + (cc + ci)) * 9 + k];
            float s = (v >= 0.f) ? 1.f : -1.f;
            swd[ci][k][co] = pk2(s, s);
        }
        __syncthreads();

#pragma unroll 2
        for (int ci = 0; ci < CI_CHUNK; ci++) {
            // packed x pairs per row: (col kw, col kw+1), kw = 0,1,2
            ull xr[3][4];
#pragma unroll
            for (int r = 0; r < 4; r++) {
                float2 a  = *(const float2*)&sx[ci][2 * py + r][2 * px];
                float2 b2 = *(const float2*)&sx[ci][2 * py + r][2 * px + 2];
                xr[0][r] = pk2(a.x, a.y);
                xr[1][r] = pk2(a.y, b2.x);
                xr[2][r] = pk2(b2.x, b2.y);
            }
#pragma unroll
            for (int kh = 0; kh < 3; kh++)
#pragma unroll
                for (int kw = 0; kw < 3; kw++) {
                    const ull* wp = &swd[ci][kh * 3 + kw][cg * 4];
                    ulonglong2 w01 = *(const ulonglong2*)wp;       // broadcast
                    ulonglong2 w23 = *(const ulonglong2*)(wp + 2); // broadcast
#pragma unroll
                    for (int dy = 0; dy < 2; dy++) {
                        ull xv = xr[kw][dy + kh];
                        ffma2(acc[dy][0], xv, w01.x);
                        ffma2(acc[dy][1], xv, w01.y);
                        ffma2(acc[dy][2], xv, w23.x);
                        ffma2(acc[dy][3], xv, w23.y);
                    }
                }
        }
        __syncthreads();
    }

    const int ph = ph0 + py, pw = pw0 + px;
    if (ph < POUT && pw < POUT) {
#pragma unroll
        for (int j = 0; j < 4; j++) {
            int co = co0 + cg * 4 + j;
            float2 a  = unpk2(acc[0][j]);
            float2 b2 = unpk2(acc[1][j]);
            float m = fmaxf(fmaxf(a.x, a.y), fmaxf(b2.x, b2.y));
            m += __ldg(&bg[co]);
            m = (m >= 0.f) ? m : LEAK * m;
            out[(((size_t)n * CO + co) * POUT + ph) * POUT + pw] = m;
        }
    }
}

// ---------------------------------------------------------------------------
// Stage 4: conv(32->8, kh=3 kw=2) + bias, no pool.
// g_buf3[32,32,26,26] -> d_out[32,4800]
// ---------------------------------------------------------------------------
__global__ __launch_bounds__(256)
void k_conv4(const float* __restrict__ w4, const float* __restrict__ b4,
             float* __restrict__ out)
{
    __shared__ float sw[8][32][3][2];
    __shared__ float sb[8];
    const int t = threadIdx.x;
    for (int i = t; i < 8 * 32 * 6; i += 256)
        ((float*)sw)[i] = (w4[i] >= 0.f) ? 1.f : -1.f;
    if (t < 8) sb[t] = b4[t];
    __syncthreads();

    int idx = blockIdx.x * 256 + t;
    if (idx >= 32 * 8 * 24 * 25) return;
    int ow = idx % 25; int r = idx / 25;
    int oh = r % 24;   r /= 24;
    int co = r % 8;    int n = r / 8;

    const float* xn = g_buf3 + ((size_t)n * 32) * (26 * 26);
    float a = sb[co];
#pragma unroll 4
    for (int ci = 0; ci < 32; ci++) {
        const float* xr = xn + ci * 676 + oh * 26 + ow;
#pragma unroll
        for (int kh = 0; kh < 3; kh++)
#pragma unroll
            for (int kw = 0; kw < 2; kw++)
                a += sw[co][ci][kh][kw] * __ldg(&xr[kh * 26 + kw]);
    }
    out[idx] = a;
}

// ---------------------------------------------------------------------------
extern "C" void kernel_launch(void* const* d_in, const int* in_sizes, int n_in,
                              void* d_out, int out_size)
{
    (void)in_sizes; (void)n_in; (void)out_size;
    const float* x  = (const float*)d_in[0];
    const float* w1 = (const float*)d_in[1];
    const float* b1 = (const float*)d_in[2];
    const float* w2 = (const float*)d_in[3];
    const float* b2 = (const float*)d_in[4];
    const float* w3 = (const float*)d_in[5];
    const float* b3 = (const float*)d_in[6];
    const float* w4 = (const float*)d_in[7];
    const float* b4 = (const float*)d_in[8];
    float* out = (float*)d_out;

    // Stage 1: pooled 111x111 -> 7x7 tiles of 16x16
    k_conv1<<<dim3(7, 7, 32), 256>>>(x, w1, b1);

    // Stage 2: CI=128 CO=64 HIN=111 POUT=54 ; spatial 7x7 tiles, 4 co-groups
    k_conv_pool<128, 64, 111, 54, 1, 2><<<dim3(49, 4, 32), 256>>>(w2, b2);

    // Stage 3: CI=64 CO=32 HIN=54 POUT=26 ; spatial 4x4 tiles, 2 co-groups
    k_conv_pool<64, 32, 54, 26, 2, 3><<<dim3(16, 2, 32), 256>>>(w3, b3);

    // Stage 4: 32*8*24*25 = 153600 outputs
    k_conv4<<<dim3((32 * 8 * 24 * 25 + 255) / 256), 256>>>(w4, b4, out);
}

// round 3
// speedup vs baseline: 2.1142x; 2.1142x over previous
#include <cuda_runtime.h>
#include <cuda_bf16.h>
#include <cstdint>

#define LEAK 0.5f

// Intermediate activation scratch (allocation-free: __device__ globals)
__device__ float g_buf1[32 * 128 * 111 * 111]; // after stage 1 (202 MB)
__device__ float g_buf2[32 * 64 * 54 * 54];    // after stage 2 (24 MB)
__device__ float g_buf3[32 * 32 * 26 * 26];    // after stage 3 (2.8 MB)

__device__ __forceinline__ float* buf_ptr(int which) {
    return which == 1 ? g_buf1 : (which == 2 ? g_buf2 : g_buf3);
}

// ---------------------------------------------------------------------------
// Stage 1: conv(1->128, 3x3) + bias + leaky + maxpool2  (scalar; K=9 only)
// x[32,1,224,224] -> g_buf1[32,128,111,111]
// ---------------------------------------------------------------------------
__global__ __launch_bounds__(256)
void k_conv1(const float* __restrict__ x, const float* __restrict__ w1,
             const float* __restrict__ b1)
{
    __shared__ __align__(16) float sx[34][36];
    __shared__ float sw[128][10];
    __shared__ float sb[128];

    const int n   = blockIdx.z;
    const int ph0 = blockIdx.y * 16, pw0 = blockIdx.x * 16;
    const int ih0 = 2 * ph0, iw0 = 2 * pw0;
    const int t   = threadIdx.x;

    const float* xn = x + (size_t)n * 224 * 224;
    for (int i = t; i < 34 * 34; i += 256) {
        int r = i / 34, c = i % 34;
        int ir = ih0 + r, ic = iw0 + c;
        sx[r][c] = (ir < 224 && ic < 224) ? xn[ir * 224 + ic] : 0.f;
    }
    for (int i = t; i < 128 * 9; i += 256)
        sw[i / 9][i % 9] = (w1[i] >= 0.f) ? 1.f : -1.f;
    if (t < 128) sb[t] = b1[t];
    __syncthreads();

    const int py = t >> 4, px = t & 15;
    const int ph = ph0 + py, pw = pw0 + px;
    const bool valid = (ph < 111) && (pw < 111);

    float xw[4][4];
#pragma unroll
    for (int r = 0; r < 4; r++)
#pragma unroll
        for (int c = 0; c < 4; c++)
            xw[r][c] = sx[2 * py + r][2 * px + c];

    float* op = g_buf1 + ((size_t)n * 128) * (111 * 111) + ph * 111 + pw;

#pragma unroll 2
    for (int co = 0; co < 128; co++) {
        float w[9];
#pragma unroll
        for (int k = 0; k < 9; k++) w[k] = sw[co][k];
        float m = -3.4e38f;
#pragma unroll
        for (int dy = 0; dy < 2; dy++)
#pragma unroll
            for (int dx = 0; dx < 2; dx++) {
                float a = 0.f;
#pragma unroll
                for (int kh = 0; kh < 3; kh++)
#pragma unroll
                    for (int kw = 0; kw < 3; kw++)
                        a += w[kh * 3 + kw] * xw[dy + kh][dx + kw];
                m = fmaxf(m, a);
            }
        m += sb[co];
        m = (m >= 0.f) ? m : LEAK * m;
        if (valid) op[(size_t)co * (111 * 111)] = m;
    }
}

// ---------------------------------------------------------------------------
// mma.sync m16n8k16 bf16 -> fp32
// ---------------------------------------------------------------------------
__device__ __forceinline__ void mma_bf16(float* d,
                                         unsigned a0, unsigned a1,
                                         unsigned a2, unsigned a3,
                                         unsigned b0, unsigned b1)
{
    asm volatile(
        "mma.sync.aligned.m16n8k16.row.col.f32.bf16.bf16.f32 "
        "{%0,%1,%2,%3}, {%4,%5,%6,%7}, {%8,%9}, {%0,%1,%2,%3};\n"
        : "+f"(d[0]), "+f"(d[1]), "+f"(d[2]), "+f"(d[3])
        : "r"(a0), "r"(a1), "r"(a2), "r"(a3), "r"(b0), "r"(b1));
}

// ---------------------------------------------------------------------------
// Stages 2/3 on tensor cores: conv(CI->CO,3x3)+bias+leaky+maxpool2.
// Implicit GEMM: M = 256 conv positions (16x16 tile -> 8x8 pooled),
// N = CO, K = CI*9 (tap loop x 16-channel chunks). Activations split into
// bf16 hi+lo (exact to ~2^-18); weights are +-1, exact in bf16.
// Block = 256 thr = 8 warps (4 M x 2 N). Warp tile 64M x CO/2 N.
// Epilogue: accumulators -> smem -> fused pool+bias+leaky -> gmem.
// ---------------------------------------------------------------------------
template<int CI, int CO, int HIN, int POUT, int IBUF, int OBUF>
__global__ __launch_bounds__(256)
void k_conv_mma(const float* __restrict__ wg, const float* __restrict__ bg)
{
    constexpr int WN   = CO / 2;          // warp N extent (32 or 16)
    constexpr int NT   = WN / 8;          // n8 tiles per warp (4 or 2)
    constexpr int NTX  = (POUT + 7) / 8;  // spatial tiles per row
    constexpr int SD   = CO + 4;          // epilogue smem stride (floats)
    constexpr int SX_E = 18 * 18 * 18;    // (y,x)=18x18, ci-slot stride 18

    extern __shared__ __align__(16) char smem_raw[];
    __nv_bfloat16* sx_hi = (__nv_bfloat16*)smem_raw;
    __nv_bfloat16* sx_lo = sx_hi + SX_E;
    __nv_bfloat16* sw    = sx_lo + SX_E;  // [9][CO][ci stride 18]

    const float* in  = buf_ptr(IBUF);
    float*       out = buf_ptr(OBUF);

    const int n   = blockIdx.z;
    const int ty  = blockIdx.x / NTX, tx = blockIdx.x % NTX;
    const int ph0 = ty * 8, pw0 = tx * 8;
    const int ih0 = 2 * ph0, iw0 = 2 * pw0;

    const int t    = threadIdx.x;
    const int lane = t & 31, w = t >> 5;
    const int wm   = w & 3, wn = w >> 2;
    const int g    = lane >> 2, tig = lane & 3;

    const float* xn = in + (size_t)n * CI * (HIN * HIN);

    float acc[4][NT][4];
#pragma unroll
    for (int mt = 0; mt < 4; mt++)
#pragma unroll
        for (int nt = 0; nt < NT; nt++)
#pragma unroll
            for (int j = 0; j < 4; j++) acc[mt][nt][j] = 0.f;

    // A-fragment base element offsets: tile mt -> conv y = 4*wm+mt, x = g
    int abase[4];
#pragma unroll
    for (int mt = 0; mt < 4; mt++)
        abase[mt] = (((4 * wm + mt) * 18) + g) * 18 + 2 * tig;

    for (int cc = 0; cc < CI; cc += 16) {
        // stage activations (fp32 -> bf16 hi/lo), channel-last, zero halo
        for (int i = t; i < 16 * 324; i += 256) {
            int ci = i / 324, rem = i % 324;
            int r = rem / 18, c = rem % 18;
            int ir = ih0 + r, ic = iw0 + c;
            float v = (ir < HIN && ic < HIN)
                          ? xn[(size_t)(cc + ci) * (HIN * HIN) + ir * HIN + ic]
                          : 0.f;
            __nv_bfloat16 h = __float2bfloat16(v);
            float lo = v - __bfloat162float(h);
            int si = (r * 18 + c) * 18 + ci;
            sx_hi[si] = h;
            sx_lo[si] = __float2bfloat16(lo);
        }
        // stage binarized weights [tap][co][ci]
        for (int i = t; i < CO * 144; i += 256) {
            int co = i / 144, rem = i % 144;
            int ci = rem / 9, tap = rem % 9;
            float v = wg[((size_t)co * CI + cc + ci) * 9 + tap];
            sw[(tap * CO + co) * 18 + ci] =
                __float2bfloat16((v >= 0.f) ? 1.f : -1.f);
        }
        __syncthreads();

#pragma unroll
        for (int kh = 0; kh < 3; kh++)
#pragma unroll
            for (int kw = 0; kw < 3; kw++) {
                const int tap  = kh * 3 + kw;
                const int toff = (kh * 18 + kw) * 18;

                unsigned b0[NT], b1[NT];
#pragma unroll
                for (int nt = 0; nt < NT; nt++) {
                    int bi = (tap * CO + wn * WN + nt * 8 + g) * 18 + 2 * tig;
                    b0[nt] = *(const unsigned*)&sw[bi];
                    b1[nt] = *(const unsigned*)&sw[bi + 8];
                }

#pragma unroll
                for (int mt = 0; mt < 4; mt++) {
                    int ai = abase[mt] + toff;
                    unsigned ah0 = *(const unsigned*)&sx_hi[ai];
                    unsigned ah2 = *(const unsigned*)&sx_hi[ai + 8];
                    unsigned ah1 = *(const unsigned*)&sx_hi[ai + 144];
                    unsigned ah3 = *(const unsigned*)&sx_hi[ai + 152];
                    unsigned al0 = *(const unsigned*)&sx_lo[ai];
                    unsigned al2 = *(const unsigned*)&sx_lo[ai + 8];
                    unsigned al1 = *(const unsigned*)&sx_lo[ai + 144];
                    unsigned al3 = *(const unsigned*)&sx_lo[ai + 152];
#pragma unroll
                    for (int nt = 0; nt < NT; nt++) {
                        mma_bf16(acc[mt][nt], ah0, ah1, ah2, ah3, b0[nt], b1[nt]);
                        mma_bf16(acc[mt][nt], al0, al1, al2, al3, b0[nt], b1[nt]);
                    }
                }
            }
        __syncthreads();
    }

    // ---- epilogue: fragments -> smem ----
    float* sd = (float*)smem_raw;
#pragma unroll
    for (int mt = 0; mt < 4; mt++) {
        int m0 = wm * 64 + mt * 16 + g;
#pragma unroll
        for (int nt = 0; nt < NT; nt++) {
            int n0 = wn * WN + nt * 8 + 2 * tig;
            *(float2*)&sd[m0 * SD + n0] =
                make_float2(acc[mt][nt][0], acc[mt][nt][1]);
            *(float2*)&sd[(m0 + 8) * SD + n0] =
                make_float2(acc[mt][nt][2], acc[mt][nt][3]);
        }
    }
    __syncthreads();

    // ---- fused maxpool(2x2) + bias + leaky ----
    {
        int pp = t >> 2, cq = t & 3;
        int py = pp >> 3, px = pp & 7;
        int ph = ph0 + py, pw = pw0 + px;
        if (ph < POUT && pw < POUT) {
            int mA = (2 * py) * 16 + 2 * px;
#pragma unroll
            for (int j = 0; j < CO / 4; j++) {
                int co = cq * (CO / 4) + j;
                float v0 = sd[mA * SD + co];
                float v1 = sd[(mA + 1) * SD + co];
                float v2 = sd[(mA + 16) * SD + co];
                float v3 = sd[(mA + 17) * SD + co];
                float m = fmaxf(fmaxf(v0, v1), fmaxf(v2, v3));
                m += __ldg(&bg[co]);
                m = (m >= 0.f) ? m : LEAK * m;
                out[(((size_t)n * CO + co) * POUT + ph) * POUT + pw] = m;
            }
        }
    }
}

// ---------------------------------------------------------------------------
// Stage 4: conv(32->8, kh=3 kw=2) + bias, no pool.
// g_buf3[32,32,26,26] -> d_out[32,4800]
// ---------------------------------------------------------------------------
__global__ __launch_bounds__(256)
void k_conv4(const float* __restrict__ w4, const float* __restrict__ b4,
             float* __restrict__ out)
{
    __shared__ float sw[8][32][3][2];
    __shared__ float sb[8];
    const int t = threadIdx.x;
    for (int i = t; i < 8 * 32 * 6; i += 256)
        ((float*)sw)[i] = (w4[i] >= 0.f) ? 1.f : -1.f;
    if (t < 8) sb[t] = b4[t];
    __syncthreads();

    int idx = blockIdx.x * 256 + t;
    if (idx >= 32 * 8 * 24 * 25) return;
    int ow = idx % 25; int r = idx / 25;
    int oh = r % 24;   r /= 24;
    int co = r % 8;    int n = r / 8;

    const float* xn = g_buf3 + ((size_t)n * 32) * (26 * 26);
    float a = sb[co];
#pragma unroll 4
    for (int ci = 0; ci < 32; ci++) {
        const float* xr = xn + ci * 676 + oh * 26 + ow;
#pragma unroll
        for (int kh = 0; kh < 3; kh++)
#pragma unroll
            for (int kw = 0; kw < 2; kw++)
                a += sw[co][ci][kh][kw] * __ldg(&xr[kh * 26 + kw]);
    }
    out[idx] = a;
}

// ---------------------------------------------------------------------------
extern "C" void kernel_launch(void* const* d_in, const int* in_sizes, int n_in,
                              void* d_out, int out_size)
{
    (void)in_sizes; (void)n_in; (void)out_size;
    const float* x  = (const float*)d_in[0];
    const float* w1 = (const float*)d_in[1];
    const float* b1 = (const float*)d_in[2];
    const float* w2 = (const float*)d_in[3];
    const float* b2 = (const float*)d_in[4];
    const float* w3 = (const float*)d_in[5];
    const float* b3 = (const float*)d_in[6];
    const float* w4 = (const float*)d_in[7];
    const float* b4 = (const float*)d_in[8];
    float* out = (float*)d_out;

    // dynamic smem: conv2 epilogue needs 256*(64+4)*4 = 69632 B (> 48K default)
    const int smem2 = 256 * (64 + 4) * 4;   // 69632
    const int smem3 = 256 * (32 + 4) * 4;   // 36864
    cudaFuncSetAttribute(k_conv_mma<128, 64, 111, 54, 1, 2>,
                         cudaFuncAttributeMaxDynamicSharedMemorySize, smem2);
    cudaFuncSetAttribute(k_conv_mma<64, 32, 54, 26, 2, 3>,
                         cudaFuncAttributeMaxDynamicSharedMemorySize, smem3);

    // Stage 1: pooled 111x111 -> 7x7 tiles of 16x16
    k_conv1<<<dim3(7, 7, 32), 256>>>(x, w1, b1);

    // Stage 2 (tensor): POUT=54 -> 7x7 tiles of 8x8 pooled
    k_conv_mma<128, 64, 111, 54, 1, 2><<<dim3(49, 1, 32), 256, smem2>>>(w2, b2);

    // Stage 3 (tensor): POUT=26 -> 4x4 tiles
    k_conv_mma<64, 32, 54, 26, 2, 3><<<dim3(16, 1, 32), 256, smem3>>>(w3, b3);

    // Stage 4: 32*8*24*25 = 153600 outputs
    k_conv4<<<dim3((32 * 8 * 24 * 25 + 255) / 256), 256>>>(w4, b4, out);
}